// round 11
// baseline (speedup 1.0000x reference)
#include <cuda_runtime.h>
#include <cuda_bf16.h>
#include <cstdint>

#define S_LEN 2048
#define D_DIM 1024
#define H_NUM 16
#define HD    64
#define B_NUM 2
#define M_TOT (B_NUM * S_LEN)   // 4096

// log2(e)/8 folded into Q projection
#define QSCALE 0.18033688011112042f

// Scratch (static device globals; no runtime allocation)
__device__ __nv_bfloat16 g_Xh[(size_t)M_TOT * D_DIM];
__device__ __nv_bfloat16 g_Xl[(size_t)M_TOT * D_DIM];
__device__ __nv_bfloat16 g_Qh[(size_t)M_TOT * D_DIM];
__device__ __nv_bfloat16 g_Ql[(size_t)M_TOT * D_DIM];
__device__ __nv_bfloat16 g_Kh[(size_t)M_TOT * D_DIM];
__device__ __nv_bfloat16 g_Kl[(size_t)M_TOT * D_DIM];
__device__ __nv_bfloat16 g_Vh[(size_t)M_TOT * D_DIM];
__device__ __nv_bfloat16 g_Vl[(size_t)M_TOT * D_DIM];
__device__ __nv_bfloat16 g_AOh[(size_t)M_TOT * D_DIM];
__device__ __nv_bfloat16 g_AOl[(size_t)M_TOT * D_DIM];
// Transposed + hi/lo-split weights (bf16, [N][K])
__device__ __nv_bfloat16 g_WQh[(size_t)D_DIM * D_DIM];
__device__ __nv_bfloat16 g_WQl[(size_t)D_DIM * D_DIM];
__device__ __nv_bfloat16 g_WKh[(size_t)D_DIM * D_DIM];
__device__ __nv_bfloat16 g_WKl[(size_t)D_DIM * D_DIM];
__device__ __nv_bfloat16 g_WVh[(size_t)D_DIM * D_DIM];
__device__ __nv_bfloat16 g_WVl[(size_t)D_DIM * D_DIM];
__device__ __nv_bfloat16 g_WOh[(size_t)D_DIM * D_DIM];
__device__ __nv_bfloat16 g_WOl[(size_t)D_DIM * D_DIM];

// ---------------------------------------------------------------------------
// helpers (base sm_103-safe PTX only: mma.sync / ldmatrix / cp.async)
// ---------------------------------------------------------------------------
__device__ __forceinline__ uint32_t smem_u32(const void* p) {
    uint32_t a;
    asm("{ .reg .u64 t; cvta.to.shared.u64 t, %1; cvt.u32.u64 %0, t; }"
        : "=r"(a) : "l"(p));
    return a;
}
__device__ __forceinline__ void cpa16(uint32_t dst, const void* src) {
    asm volatile("cp.async.cg.shared.global [%0], [%1], 16;"
                 :: "r"(dst), "l"(src) : "memory");
}
__device__ __forceinline__ void cpa_commit() {
    asm volatile("cp.async.commit_group;" ::: "memory");
}
template <int N> __device__ __forceinline__ void cpa_wait() {
    asm volatile("cp.async.wait_group %0;" :: "n"(N) : "memory");
}
__device__ __forceinline__ void ldsm4(uint32_t* r, uint32_t addr) {
    asm volatile("ldmatrix.sync.aligned.m8n8.x4.shared.b16 {%0,%1,%2,%3}, [%4];"
                 : "=r"(r[0]), "=r"(r[1]), "=r"(r[2]), "=r"(r[3]) : "r"(addr));
}
__device__ __forceinline__ void ldsm4t(uint32_t* r, uint32_t addr) {
    asm volatile("ldmatrix.sync.aligned.m8n8.x4.trans.shared.b16 {%0,%1,%2,%3}, [%4];"
                 : "=r"(r[0]), "=r"(r[1]), "=r"(r[2]), "=r"(r[3]) : "r"(addr));
}
__device__ __forceinline__ void mma16816(float* c, const uint32_t* a,
                                         uint32_t b0, uint32_t b1) {
    asm volatile(
        "mma.sync.aligned.m16n8k16.row.col.f32.bf16.bf16.f32 "
        "{%0,%1,%2,%3}, {%4,%5,%6,%7}, {%8,%9}, {%0,%1,%2,%3};"
        : "+f"(c[0]), "+f"(c[1]), "+f"(c[2]), "+f"(c[3])
        : "r"(a[0]), "r"(a[1]), "r"(a[2]), "r"(a[3]), "r"(b0), "r"(b1));
}
__device__ __forceinline__ float ex2f(float x) {
    float y;
    asm("ex2.approx.ftz.f32 %0, %1;" : "=f"(y) : "f"(x));
    return y;
}
__device__ __forceinline__ uint32_t packbf(float a, float b) {
    __nv_bfloat162 t = __floats2bfloat162_rn(a, b);
    return *(uint32_t*)&t;
}

// ---------------------------------------------------------------------------
// split: fp32 -> bf16 hi + bf16 residual (activations x)
// ---------------------------------------------------------------------------
__global__ __launch_bounds__(256) void split_fp32(
    const float* __restrict__ X,
    __nv_bfloat16* __restrict__ H, __nv_bfloat16* __restrict__ L)
{
    const int i = (blockIdx.x * 256 + threadIdx.x) * 4;
    float4 v = *(const float4*)(X + i);
    float f[4] = {v.x, v.y, v.z, v.w};
    __nv_bfloat16 h[4], l[4];
#pragma unroll
    for (int e = 0; e < 4; e++) {
        h[e] = __float2bfloat16(f[e]);
        l[e] = __float2bfloat16(f[e] - __bfloat162float(h[e]));
    }
    *(uint2*)(H + i) = *(const uint2*)h;
    *(uint2*)(L + i) = *(const uint2*)l;
}

// ---------------------------------------------------------------------------
// Transpose + hi/lo split weights: Th[n][k] = bf16(W[k][n]), Tl = residual.
// ---------------------------------------------------------------------------
__global__ __launch_bounds__(256) void transpose_split(
    const float* __restrict__ W,
    __nv_bfloat16* __restrict__ Th, __nv_bfloat16* __restrict__ Tl)
{
    __shared__ float tile[32][33];
    const int n0 = blockIdx.x * 32, k0 = blockIdx.y * 32;
    const int tx = threadIdx.x, ty = threadIdx.y;   // (32, 8)
#pragma unroll
    for (int i = 0; i < 32; i += 8)
        tile[ty + i][tx] = W[(size_t)(k0 + ty + i) * D_DIM + n0 + tx];
    __syncthreads();
#pragma unroll
    for (int i = 0; i < 32; i += 8) {
        float v = tile[tx][ty + i];
        __nv_bfloat16 h = __float2bfloat16(v);
        __nv_bfloat16 l = __float2bfloat16(v - __bfloat162float(h));
        size_t o = (size_t)(n0 + ty + i) * D_DIM + k0 + tx;
        Th[o] = h;
        Tl[o] = l;
    }
}

// ---------------------------------------------------------------------------
// bf16x3 HMMA GEMM. OUTM=0: fp32 C out. OUTM=1: bf16 hi/lo out, scaled.
// CTA 256x128, K-chunk 32, 2-stage cp.async pipeline, 16 warps (4x4),
// warp tile 64x32, mma.m16n8k16, products Ah*Bh + Ah*Bl + Al*Bh.
// ---------------------------------------------------------------------------
#define LDH_B 80                 // bytes per smem row (32 bf16 + pad)
#define A_BYTES (256 * LDH_B)    // 20480
#define B_BYTES (128 * LDH_B)    // 10240
#define OFF_AH 0
#define OFF_AL A_BYTES
#define OFF_BH (2 * A_BYTES)
#define OFF_BL (2 * A_BYTES + B_BYTES)
#define STG_BYTES (2 * A_BYTES + 2 * B_BYTES)   // 61440
#define GEMM_SMEM (2 * STG_BYTES)               // 122880
#define NSTAGE (D_DIM / 32)      // 32

template <int OUTM>
__global__ __launch_bounds__(512) void gemm_mma(
    const __nv_bfloat16* __restrict__ Ah, const __nv_bfloat16* __restrict__ Al,
    const __nv_bfloat16* __restrict__ Bh, const __nv_bfloat16* __restrict__ Bl,
    float* __restrict__ C,
    __nv_bfloat16* __restrict__ Ch, __nv_bfloat16* __restrict__ Cl,
    float scale)
{
    extern __shared__ char smraw[];
    const uint32_t smb = smem_u32(smraw);
    const int tid = threadIdx.x, lane = tid & 31, wid = tid >> 5;
    const int wm = wid >> 2, wn = wid & 3;
    const int bm = blockIdx.y, bn = blockIdx.x;

    float acc[4][4][4];
#pragma unroll
    for (int i = 0; i < 4; i++)
#pragma unroll
        for (int j = 0; j < 4; j++)
#pragma unroll
            for (int e = 0; e < 4; e++) acc[i][j][e] = 0.0f;

#define ISSUE_STAGE(s)                                                        \
    {                                                                         \
        const uint32_t sb_ = smb + ((s) & 1) * STG_BYTES;                     \
        _Pragma("unroll")                                                     \
        for (int q = 0; q < 2; q++) {                                         \
            const int id = tid + q * 512;                                     \
            const int r = id >> 2, c = id & 3;                                \
            const uint32_t off = (uint32_t)(r * LDH_B + c * 16);              \
            const size_t ga = (size_t)(bm * 256 + r) * D_DIM + (s) * 32 + c * 8; \
            cpa16(sb_ + OFF_AH + off, Ah + ga);                               \
            cpa16(sb_ + OFF_AL + off, Al + ga);                               \
        }                                                                     \
        {                                                                     \
            const int r = tid >> 2, c = tid & 3;                              \
            const uint32_t off = (uint32_t)(r * LDH_B + c * 16);              \
            const size_t gb = (size_t)(bn * 128 + r) * D_DIM + (s) * 32 + c * 8; \
            cpa16(sb_ + OFF_BH + off, Bh + gb);                               \
            cpa16(sb_ + OFF_BL + off, Bl + gb);                               \
        }                                                                     \
        cpa_commit();                                                         \
    }

    ISSUE_STAGE(0);

    for (int s = 0; s < NSTAGE; s++) {
        if (s + 1 < NSTAGE) {
            ISSUE_STAGE(s + 1);
            cpa_wait<1>();
        } else {
            cpa_wait<0>();
        }
        __syncthreads();

        const uint32_t sb = smb + (s & 1) * STG_BYTES;
        const uint32_t arow = (uint32_t)((wm * 64 + (lane & 15)) * LDH_B +
                                         (lane >> 4) * 16);
        const uint32_t brow = (uint32_t)((wn * 32 + ((lane >> 4) & 1) * 8 +
                                          (lane & 7)) * LDH_B +
                                         ((lane >> 3) & 1) * 16);
#pragma unroll
        for (int ks = 0; ks < 2; ks++) {
            uint32_t bh[4][2], bl[4][2];
#pragma unroll
            for (int t = 0; t < 2; t++) {
                uint32_t r4[4];
                const uint32_t bo = brow + (uint32_t)(t * 16 * LDH_B + ks * 32);
                ldsm4(r4, sb + OFF_BH + bo);
                bh[2 * t][0] = r4[0]; bh[2 * t][1] = r4[1];
                bh[2 * t + 1][0] = r4[2]; bh[2 * t + 1][1] = r4[3];
                ldsm4(r4, sb + OFF_BL + bo);
                bl[2 * t][0] = r4[0]; bl[2 * t][1] = r4[1];
                bl[2 * t + 1][0] = r4[2]; bl[2 * t + 1][1] = r4[3];
            }
#pragma unroll
            for (int mt = 0; mt < 4; mt++) {
                uint32_t ah[4], al[4];
                const uint32_t ao = arow + (uint32_t)(mt * 16 * LDH_B + ks * 32);
                ldsm4(ah, sb + OFF_AH + ao);
                ldsm4(al, sb + OFF_AL + ao);
#pragma unroll
                for (int nt = 0; nt < 4; nt++) {
                    mma16816(acc[mt][nt], ah, bh[nt][0], bh[nt][1]);
                    mma16816(acc[mt][nt], ah, bl[nt][0], bl[nt][1]);
                    mma16816(acc[mt][nt], al, bh[nt][0], bh[nt][1]);
                }
            }
        }
        __syncthreads();
    }

    // epilogue
    const int rg = lane >> 2, cg = (lane & 3) * 2;
#pragma unroll
    for (int mt = 0; mt < 4; mt++) {
        const int row = bm * 256 + wm * 64 + mt * 16 + rg;
#pragma unroll
        for (int nt = 0; nt < 4; nt++) {
            const int col = bn * 128 + wn * 32 + nt * 8 + cg;
            if (OUTM == 0) {
                *(float2*)(C + (size_t)row * D_DIM + col) =
                    make_float2(acc[mt][nt][0], acc[mt][nt][1]);
                *(float2*)(C + (size_t)(row + 8) * D_DIM + col) =
                    make_float2(acc[mt][nt][2], acc[mt][nt][3]);
            } else {
#pragma unroll
                for (int rh = 0; rh < 2; rh++) {
                    float v0 = acc[mt][nt][2 * rh] * scale;
                    float v1 = acc[mt][nt][2 * rh + 1] * scale;
                    __nv_bfloat16 h0 = __float2bfloat16(v0);
                    __nv_bfloat16 h1 = __float2bfloat16(v1);
                    float l0 = v0 - __bfloat162float(h0);
                    float l1 = v1 - __bfloat162float(h1);
                    const size_t o = (size_t)(row + rh * 8) * D_DIM + col;
                    __nv_bfloat162 hp; hp.x = h0; hp.y = h1;
                    *(uint32_t*)(Ch + o) = *(uint32_t*)&hp;
                    *(uint32_t*)(Cl + o) = packbf(l0, l1);
                }
            }
        }
    }
#undef ISSUE_STAGE
}

// ---------------------------------------------------------------------------
// HMMA flash attention (causal). CTA: 128 q-rows x 1 head. 8 warps x 16 rows.
// Bk=64, K/V double-buffered cp.async with SPLIT K/V commit groups:
// wait K before QK, wait V only before PV (V load hides under QK+softmax).
// bf16x3 for QK and PV. exp2-domain softmax. Writes bf16 hi/lo output.
// ---------------------------------------------------------------------------
#define FQ_BYTES (128 * 144)            // 18432 per Q array
#define FKV_ARR  (64 * 144)             // 9216 per K/V array
#define FKV_STG  (4 * FKV_ARR)          // 36864 per stage
#define FLASH_SMEM (2 * FQ_BYTES + 2 * FKV_STG)   // 110592

__global__ __launch_bounds__(256) void flash_mma(
    const __nv_bfloat16* __restrict__ Qh, const __nv_bfloat16* __restrict__ Ql,
    const __nv_bfloat16* __restrict__ Kh, const __nv_bfloat16* __restrict__ Kl,
    const __nv_bfloat16* __restrict__ Vh, const __nv_bfloat16* __restrict__ Vl,
    __nv_bfloat16* __restrict__ Oh, __nv_bfloat16* __restrict__ Ol)
{
    extern __shared__ char fsm[];
    const uint32_t smb = smem_u32(fsm);
    const int tid = threadIdx.x, lane = tid & 31, wm = tid >> 5;
    const int bq = (int)gridDim.x - 1 - (int)blockIdx.x;   // heavy blocks first
    const int hh = blockIdx.y, bb = blockIdx.z;
    const int q0 = bq * 128;
    const int nt = 2 * bq + 2;
    const size_t rowbase = (size_t)bb * S_LEN;
    const int coff = hh * HD;

    const uint32_t QHs = smb, QLs = smb + FQ_BYTES, KVs = smb + 2 * FQ_BYTES;

    // issue Q tile (joins the first K commit group)
#pragma unroll
    for (int i = 0; i < 4; i++) {
        int id = tid + i * 256;
        int r = id >> 3, c = id & 7;
        size_t g = (rowbase + q0 + r) * D_DIM + coff + c * 8;
        uint32_t d = (uint32_t)(r * 144 + c * 16);
        cpa16(QHs + d, Qh + g);
        cpa16(QLs + d, Ql + g);
    }

#define ISSUE_K(t_, st_)                                                     \
    {                                                                        \
        const uint32_t base_ = KVs + (st_) * FKV_STG;                        \
        const int k0_ = (t_) * 64;                                           \
        _Pragma("unroll")                                                    \
        for (int i = 0; i < 2; i++) {                                        \
            int id = tid + i * 256;                                          \
            int r = id >> 3, c = id & 7;                                     \
            size_t g = (rowbase + k0_ + r) * D_DIM + coff + c * 8;           \
            uint32_t d = (uint32_t)(r * 144 + c * 16);                       \
            cpa16(base_ + d, Kh + g);                                        \
            cpa16(base_ + FKV_ARR + d, Kl + g);                              \
        }                                                                    \
        cpa_commit();                                                        \
    }
#define ISSUE_V(t_, st_)                                                     \
    {                                                                        \
        const uint32_t base_ = KVs + (st_) * FKV_STG;                        \
        const int k0_ = (t_) * 64;                                           \
        _Pragma("unroll")                                                    \
        for (int i = 0; i < 2; i++) {                                        \
            int id = tid + i * 256;                                          \
            int r = id >> 3, c = id & 7;                                     \
            size_t g = (rowbase + k0_ + r) * D_DIM + coff + c * 8;           \
            uint32_t d = (uint32_t)(r * 144 + c * 16);                       \
            cpa16(base_ + 2 * FKV_ARR + d, Vh + g);                          \
            cpa16(base_ + 3 * FKV_ARR + d, Vl + g);                          \
        }                                                                    \
        cpa_commit();                                                        \
    }

    // prologue: groups = {Q+K0}, {V0}, {K1}, {V1}
    ISSUE_K(0, 0);
    ISSUE_V(0, 0);
    ISSUE_K(1, 1);
    ISSUE_V(1, 1);

    // K0 (and Q) ready: pending after group0 = V0,K1,V1 = 3
    cpa_wait<3>();
    __syncthreads();

    // Q fragments -> registers (stay for whole CTA)
    uint32_t qfh[4][4], qfl[4][4];
    {
        const uint32_t qoff = (uint32_t)((wm * 16 + (lane & 15)) * 144 +
                                         ((lane >> 4) & 1) * 16);
#pragma unroll
        for (int k = 0; k < 4; k++) {
            ldsm4(qfh[k], QHs + qoff + k * 32);
            ldsm4(qfl[k], QLs + qoff + k * 32);
        }
    }

    float O[8][4];
#pragma unroll
    for (int j = 0; j < 8; j++)
#pragma unroll
        for (int e = 0; e < 4; e++) O[j][e] = 0.0f;
    float mo[2] = {-1e30f, -1e30f}, ls[2] = {0.0f, 0.0f};

    const int qb = q0 + wm * 16;

    for (int t = 0; t < nt; t++) {
        const uint32_t sb = KVs + (t & 1) * FKV_STG;
        const int k0 = t * 64;

        if (t > 0) {
            // K(t) ready: steady-state pending = V(t),K(t+1),V(t+1)
            if (t < nt - 1) cpa_wait<3>(); else cpa_wait<1>();
            __syncthreads();
        }

        // ---- S = Qs K^T (exp2 domain; scale folded into Q) ----
        float S[8][4];
#pragma unroll
        for (int j = 0; j < 8; j++)
#pragma unroll
            for (int e = 0; e < 4; e++) S[j][e] = 0.0f;

        const uint32_t krow = (uint32_t)(((lane & 7) + ((lane >> 4) & 1) * 8) * 144 +
                                         ((lane >> 3) & 1) * 16);
#pragma unroll
        for (int j2 = 0; j2 < 4; j2++) {
#pragma unroll
            for (int k = 0; k < 4; k++) {
                uint32_t bh[4], bl[4];
                const uint32_t ka = sb + krow + (uint32_t)(j2 * 16 * 144 + k * 32);
                ldsm4(bh, ka);
                ldsm4(bl, ka + FKV_ARR);
                mma16816(S[2 * j2], qfh[k], bh[0], bh[1]);
                mma16816(S[2 * j2], qfh[k], bl[0], bl[1]);
                mma16816(S[2 * j2], qfl[k], bh[0], bh[1]);
                mma16816(S[2 * j2 + 1], qfh[k], bh[2], bh[3]);
                mma16816(S[2 * j2 + 1], qfh[k], bl[2], bl[3]);
                mma16816(S[2 * j2 + 1], qfl[k], bh[2], bh[3]);
            }
        }

        // ---- causal mask ----
        if (k0 + 63 > qb) {
#pragma unroll
            for (int j = 0; j < 8; j++)
#pragma unroll
                for (int e = 0; e < 4; e++) {
                    int kj = k0 + j * 8 + (lane & 3) * 2 + (e & 1);
                    int qi = qb + (lane >> 2) + (e >> 1) * 8;
                    if (kj > qi) S[j][e] = -1e30f;
                }
        }

        // ---- online softmax (exp2 domain), per row-half ----
#pragma unroll
        for (int rh = 0; rh < 2; rh++) {
            float mx = -1e30f;
#pragma unroll
            for (int j = 0; j < 8; j++) {
                mx = fmaxf(mx, S[j][2 * rh]);
                mx = fmaxf(mx, S[j][2 * rh + 1]);
            }
            mx = fmaxf(mx, __shfl_xor_sync(0xffffffffu, mx, 1));
            mx = fmaxf(mx, __shfl_xor_sync(0xffffffffu, mx, 2));
            const float mn = fmaxf(mo[rh], mx);
            const float cc = ex2f(mo[rh] - mn);
            mo[rh] = mn;
            float ps = 0.0f;
#pragma unroll
            for (int j = 0; j < 8; j++) {
                float p0 = ex2f(S[j][2 * rh] - mn);
                float p1 = ex2f(S[j][2 * rh + 1] - mn);
                S[j][2 * rh] = p0;
                S[j][2 * rh + 1] = p1;
                ps += p0 + p1;
            }
            ps += __shfl_xor_sync(0xffffffffu, ps, 1);
            ps += __shfl_xor_sync(0xffffffffu, ps, 2);
            ls[rh] = ls[rh] * cc + ps;
#pragma unroll
            for (int j = 0; j < 8; j++) {
                O[j][2 * rh] *= cc;
                O[j][2 * rh + 1] *= cc;
            }
        }

        // ---- pack P -> A fragments (hi/lo) ----
        uint32_t aph[4][4], apl[4][4];
#pragma unroll
        for (int k = 0; k < 4; k++)
#pragma unroll
            for (int r = 0; r < 4; r++) {
                const int tl = 2 * k + (r >> 1);
                const int pr = (r & 1) * 2;
                float x0 = S[tl][pr], x1 = S[tl][pr + 1];
                __nv_bfloat16 h0 = __float2bfloat16(x0);
                __nv_bfloat16 h1 = __float2bfloat16(x1);
                __nv_bfloat162 hp; hp.x = h0; hp.y = h1;
                aph[k][r] = *(uint32_t*)&hp;
                apl[k][r] = packbf(x0 - __bfloat162float(h0),
                                   x1 - __bfloat162float(h1));
            }

        // V(t) ready: steady-state pending = K(t+1),V(t+1)
        if (t < nt - 1) cpa_wait<2>(); else cpa_wait<0>();
        __syncthreads();

        // ---- O += P V  (V via ldmatrix.trans) ----
        const uint32_t vrow = (uint32_t)(((lane & 7) + ((lane >> 3) & 1) * 8) * 144 +
                                         ((lane >> 4) & 1) * 16);
#pragma unroll
        for (int dj = 0; dj < 4; dj++) {
#pragma unroll
            for (int k = 0; k < 4; k++) {
                uint32_t bh[4], bl[4];
                const uint32_t va = sb + 2 * FKV_ARR + vrow +
                                    (uint32_t)(k * 16 * 144 + dj * 32);
                ldsm4t(bh, va);
                ldsm4t(bl, va + FKV_ARR);
                mma16816(O[2 * dj], aph[k], bh[0], bh[1]);
                mma16816(O[2 * dj], aph[k], bl[0], bl[1]);
                mma16816(O[2 * dj], apl[k], bh[0], bh[1]);
                mma16816(O[2 * dj + 1], aph[k], bh[2], bh[3]);
                mma16816(O[2 * dj + 1], aph[k], bl[2], bl[3]);
                mma16816(O[2 * dj + 1], apl[k], bh[2], bh[3]);
            }
        }

        // buffer (t&1) fully consumed -> prefetch tile t+2 into it
        __syncthreads();
        if (t + 2 < nt) {
            ISSUE_K(t + 2, (t & 1));
            ISSUE_V(t + 2, (t & 1));
        }
    }

    // ---- epilogue: normalize, split, store bf16 hi/lo ----
    const float inv[2] = {1.0f / ls[0], 1.0f / ls[1]};
#pragma unroll
    for (int j = 0; j < 8; j++)
#pragma unroll
        for (int rh = 0; rh < 2; rh++) {
            float o0 = O[j][2 * rh] * inv[rh];
            float o1 = O[j][2 * rh + 1] * inv[rh];
            __nv_bfloat16 h0 = __float2bfloat16(o0);
            __nv_bfloat16 h1 = __float2bfloat16(o1);
            const size_t row = rowbase + q0 + wm * 16 + (lane >> 2) + rh * 8;
            const int col = coff + j * 8 + (lane & 3) * 2;
            __nv_bfloat162 hp; hp.x = h0; hp.y = h1;
            *(uint32_t*)(Oh + row * D_DIM + col) = *(uint32_t*)&hp;
            *(uint32_t*)(Ol + row * D_DIM + col) =
                packbf(o0 - __bfloat162float(h0), o1 - __bfloat162float(h1));
        }
#undef ISSUE_K
#undef ISSUE_V
}

extern "C" void kernel_launch(void* const* d_in, const int* in_sizes, int n_in,
                              void* d_out, int out_size)
{
    (void)in_sizes; (void)n_in; (void)out_size;
    const float* x  = (const float*)d_in[0];
    const float* WQ = (const float*)d_in[1];
    const float* WK = (const float*)d_in[2];
    const float* WV = (const float*)d_in[3];
    const float* WO = (const float*)d_in[4];
    float* out = (float*)d_out;

    __nv_bfloat16 *Xh, *Xl, *Qh, *Ql, *Kh, *Kl, *Vh, *Vl, *AOh, *AOl;
    cudaGetSymbolAddress((void**)&Xh, g_Xh);
    cudaGetSymbolAddress((void**)&Xl, g_Xl);
    cudaGetSymbolAddress((void**)&Qh, g_Qh);
    cudaGetSymbolAddress((void**)&Ql, g_Ql);
    cudaGetSymbolAddress((void**)&Kh, g_Kh);
    cudaGetSymbolAddress((void**)&Kl, g_Kl);
    cudaGetSymbolAddress((void**)&Vh, g_Vh);
    cudaGetSymbolAddress((void**)&Vl, g_Vl);
    cudaGetSymbolAddress((void**)&AOh, g_AOh);
    cudaGetSymbolAddress((void**)&AOl, g_AOl);
    __nv_bfloat16 *WQh, *WQl, *WKh, *WKl, *WVh, *WVl, *WOh, *WOl;
    cudaGetSymbolAddress((void**)&WQh, g_WQh);
    cudaGetSymbolAddress((void**)&WQl, g_WQl);
    cudaGetSymbolAddress((void**)&WKh, g_WKh);
    cudaGetSymbolAddress((void**)&WKl, g_WKl);
    cudaGetSymbolAddress((void**)&WVh, g_WVh);
    cudaGetSymbolAddress((void**)&WVl, g_WVl);
    cudaGetSymbolAddress((void**)&WOh, g_WOh);
    cudaGetSymbolAddress((void**)&WOl, g_WOl);

    // weight transpose+split and activation split
    dim3 tg(D_DIM / 32, D_DIM / 32);
    dim3 tb(32, 8);
    transpose_split<<<tg, tb>>>(WQ, WQh, WQl);
    transpose_split<<<tg, tb>>>(WK, WKh, WKl);
    transpose_split<<<tg, tb>>>(WV, WVh, WVl);
    transpose_split<<<tg, tb>>>(WO, WOh, WOl);
    split_fp32<<<(M_TOT * D_DIM) / (256 * 4), 256>>>(x, Xh, Xl);

    cudaFuncSetAttribute(gemm_mma<0>, cudaFuncAttributeMaxDynamicSharedMemorySize,
                         GEMM_SMEM);
    cudaFuncSetAttribute(gemm_mma<1>, cudaFuncAttributeMaxDynamicSharedMemorySize,
                         GEMM_SMEM);
    dim3 gg(D_DIM / 128, M_TOT / 256);   // (8, 16)
    // projections emit bf16 hi/lo directly; Q carries log2e/8
    gemm_mma<1><<<gg, 512, GEMM_SMEM>>>(Xh, Xl, WQh, WQl, nullptr, Qh, Ql, QSCALE);
    gemm_mma<1><<<gg, 512, GEMM_SMEM>>>(Xh, Xl, WKh, WKl, nullptr, Kh, Kl, 1.0f);
    gemm_mma<1><<<gg, 512, GEMM_SMEM>>>(Xh, Xl, WVh, WVl, nullptr, Vh, Vl, 1.0f);

    cudaFuncSetAttribute(flash_mma, cudaFuncAttributeMaxDynamicSharedMemorySize,
                         FLASH_SMEM);
    flash_mma<<<dim3(S_LEN / 128, H_NUM, B_NUM), 256, FLASH_SMEM>>>(
        Qh, Ql, Kh, Kl, Vh, Vl, AOh, AOl);

    gemm_mma<0><<<gg, 512, GEMM_SMEM>>>(AOh, AOl, WOh, WOl, out, nullptr, nullptr,
                                        1.0f);
}

// round 14
// speedup vs baseline: 1.4478x; 1.4478x over previous
#include <cuda_runtime.h>
#include <cuda_bf16.h>
#include <cstdint>

#define S_LEN 2048
#define D_DIM 1024
#define H_NUM 16
#define HD    64
#define B_NUM 2
#define M_TOT (B_NUM * S_LEN)   // 4096

// log2(e)/8 folded into Q projection
#define QSCALE 0.18033688011112042f

// Scratch (static device globals; no runtime allocation)
__device__ __nv_bfloat16 g_Xh[(size_t)M_TOT * D_DIM];
__device__ __nv_bfloat16 g_Xl[(size_t)M_TOT * D_DIM];
__device__ __nv_bfloat16 g_Qh[(size_t)M_TOT * D_DIM];
__device__ __nv_bfloat16 g_Ql[(size_t)M_TOT * D_DIM];
__device__ __nv_bfloat16 g_Kh[(size_t)M_TOT * D_DIM];
__device__ __nv_bfloat16 g_Kl[(size_t)M_TOT * D_DIM];
__device__ __nv_bfloat16 g_Vh[(size_t)M_TOT * D_DIM];
__device__ __nv_bfloat16 g_Vl[(size_t)M_TOT * D_DIM];
__device__ __nv_bfloat16 g_AOh[(size_t)M_TOT * D_DIM];
__device__ __nv_bfloat16 g_AOl[(size_t)M_TOT * D_DIM];
// Transposed + hi/lo-split weights (bf16, [N][K])
__device__ __nv_bfloat16 g_WQh[(size_t)D_DIM * D_DIM];
__device__ __nv_bfloat16 g_WQl[(size_t)D_DIM * D_DIM];
__device__ __nv_bfloat16 g_WKh[(size_t)D_DIM * D_DIM];
__device__ __nv_bfloat16 g_WKl[(size_t)D_DIM * D_DIM];
__device__ __nv_bfloat16 g_WVh[(size_t)D_DIM * D_DIM];
__device__ __nv_bfloat16 g_WVl[(size_t)D_DIM * D_DIM];
__device__ __nv_bfloat16 g_WOh[(size_t)D_DIM * D_DIM];
__device__ __nv_bfloat16 g_WOl[(size_t)D_DIM * D_DIM];

// ---------------------------------------------------------------------------
// helpers (base sm_103-safe PTX only: mma.sync / ldmatrix / cp.async)
// ---------------------------------------------------------------------------
__device__ __forceinline__ uint32_t smem_u32(const void* p) {
    uint32_t a;
    asm("{ .reg .u64 t; cvta.to.shared.u64 t, %1; cvt.u32.u64 %0, t; }"
        : "=r"(a) : "l"(p));
    return a;
}
__device__ __forceinline__ void cpa16(uint32_t dst, const void* src) {
    asm volatile("cp.async.cg.shared.global [%0], [%1], 16;"
                 :: "r"(dst), "l"(src) : "memory");
}
__device__ __forceinline__ void cpa_commit() {
    asm volatile("cp.async.commit_group;" ::: "memory");
}
template <int N> __device__ __forceinline__ void cpa_wait() {
    asm volatile("cp.async.wait_group %0;" :: "n"(N) : "memory");
}
__device__ __forceinline__ void ldsm4(uint32_t* r, uint32_t addr) {
    asm volatile("ldmatrix.sync.aligned.m8n8.x4.shared.b16 {%0,%1,%2,%3}, [%4];"
                 : "=r"(r[0]), "=r"(r[1]), "=r"(r[2]), "=r"(r[3]) : "r"(addr));
}
__device__ __forceinline__ void ldsm4t(uint32_t* r, uint32_t addr) {
    asm volatile("ldmatrix.sync.aligned.m8n8.x4.trans.shared.b16 {%0,%1,%2,%3}, [%4];"
                 : "=r"(r[0]), "=r"(r[1]), "=r"(r[2]), "=r"(r[3]) : "r"(addr));
}
__device__ __forceinline__ void mma16816(float* c, const uint32_t* a,
                                         uint32_t b0, uint32_t b1) {
    asm volatile(
        "mma.sync.aligned.m16n8k16.row.col.f32.bf16.bf16.f32 "
        "{%0,%1,%2,%3}, {%4,%5,%6,%7}, {%8,%9}, {%0,%1,%2,%3};"
        : "+f"(c[0]), "+f"(c[1]), "+f"(c[2]), "+f"(c[3])
        : "r"(a[0]), "r"(a[1]), "r"(a[2]), "r"(a[3]), "r"(b0), "r"(b1));
}
__device__ __forceinline__ float ex2f(float x) {
    float y;
    asm("ex2.approx.ftz.f32 %0, %1;" : "=f"(y) : "f"(x));
    return y;
}
__device__ __forceinline__ uint32_t packbf(float a, float b) {
    __nv_bfloat162 t = __floats2bfloat162_rn(a, b);
    return *(uint32_t*)&t;
}

// ---------------------------------------------------------------------------
// split: fp32 -> bf16 hi + bf16 residual (activations x)
// ---------------------------------------------------------------------------
__global__ __launch_bounds__(256) void split_fp32(
    const float* __restrict__ X,
    __nv_bfloat16* __restrict__ H, __nv_bfloat16* __restrict__ L)
{
    const int i = (blockIdx.x * 256 + threadIdx.x) * 4;
    float4 v = *(const float4*)(X + i);
    float f[4] = {v.x, v.y, v.z, v.w};
    __nv_bfloat16 h[4], l[4];
#pragma unroll
    for (int e = 0; e < 4; e++) {
        h[e] = __float2bfloat16(f[e]);
        l[e] = __float2bfloat16(f[e] - __bfloat162float(h[e]));
    }
    *(uint2*)(H + i) = *(const uint2*)h;
    *(uint2*)(L + i) = *(const uint2*)l;
}

// ---------------------------------------------------------------------------
// Transpose + hi/lo split weights: Th[n][k] = bf16(W[k][n]), Tl = residual.
// ---------------------------------------------------------------------------
__global__ __launch_bounds__(256) void transpose_split(
    const float* __restrict__ W,
    __nv_bfloat16* __restrict__ Th, __nv_bfloat16* __restrict__ Tl)
{
    __shared__ float tile[32][33];
    const int n0 = blockIdx.x * 32, k0 = blockIdx.y * 32;
    const int tx = threadIdx.x, ty = threadIdx.y;   // (32, 8)
#pragma unroll
    for (int i = 0; i < 32; i += 8)
        tile[ty + i][tx] = W[(size_t)(k0 + ty + i) * D_DIM + n0 + tx];
    __syncthreads();
#pragma unroll
    for (int i = 0; i < 32; i += 8) {
        float v = tile[tx][ty + i];
        __nv_bfloat16 h = __float2bfloat16(v);
        __nv_bfloat16 l = __float2bfloat16(v - __bfloat162float(h));
        size_t o = (size_t)(n0 + ty + i) * D_DIM + k0 + tx;
        Th[o] = h;
        Tl[o] = l;
    }
}

// ---------------------------------------------------------------------------
// bf16x3 HMMA GEMM. OUTM=0: fp32 C out. OUTM=1: bf16 hi/lo out, scaled.
// CTA 128x128, K-chunk 32, 4-stage cp.async pipeline, 8 warps (2x4),
// warp tile 64x32, mma.m16n8k16, products Ah*Bh + Ah*Bl + Al*Bh.
// ---------------------------------------------------------------------------
#define LDH_B 80                 // bytes per smem row
#define ARR_BYTES (128 * LDH_B)  // 10240 per array
#define STG_BYTES (4 * ARR_BYTES)
#define OFF_AH 0
#define OFF_AL ARR_BYTES
#define OFF_BH (2 * ARR_BYTES)
#define OFF_BL (3 * ARR_BYTES)
#define NPIPE 4
#define GEMM_SMEM (NPIPE * STG_BYTES)   // 163840
#define NSTAGE (D_DIM / 32)      // 32

template <int OUTM>
__global__ __launch_bounds__(256) void gemm_mma(
    const __nv_bfloat16* __restrict__ Ah, const __nv_bfloat16* __restrict__ Al,
    const __nv_bfloat16* __restrict__ Bh, const __nv_bfloat16* __restrict__ Bl,
    float* __restrict__ C,
    __nv_bfloat16* __restrict__ Ch, __nv_bfloat16* __restrict__ Cl,
    float scale)
{
    extern __shared__ char smraw[];
    const uint32_t smb = smem_u32(smraw);
    const int tid = threadIdx.x, lane = tid & 31, wid = tid >> 5;
    const int wm = wid >> 2, wn = wid & 3;
    const int bm = blockIdx.y, bn = blockIdx.x;

    float acc[4][4][4];
#pragma unroll
    for (int i = 0; i < 4; i++)
#pragma unroll
        for (int j = 0; j < 4; j++)
#pragma unroll
            for (int e = 0; e < 4; e++) acc[i][j][e] = 0.0f;

#define ISSUE_STAGE(s)                                                        \
    {                                                                         \
        const uint32_t sb_ = smb + ((s) & (NPIPE - 1)) * STG_BYTES;           \
        _Pragma("unroll")                                                     \
        for (int q = 0; q < 2; q++) {                                         \
            const int id = tid + q * 256;                                     \
            const int r = id >> 2, c = id & 3;                                \
            const uint32_t off = (uint32_t)(r * LDH_B + c * 16);              \
            const size_t ga = (size_t)(bm * 128 + r) * D_DIM + (s) * 32 + c * 8; \
            const size_t gb = (size_t)(bn * 128 + r) * D_DIM + (s) * 32 + c * 8; \
            cpa16(sb_ + OFF_AH + off, Ah + ga);                               \
            cpa16(sb_ + OFF_AL + off, Al + ga);                               \
            cpa16(sb_ + OFF_BH + off, Bh + gb);                               \
            cpa16(sb_ + OFF_BL + off, Bl + gb);                               \
        }                                                                     \
        cpa_commit();                                                         \
    }

    ISSUE_STAGE(0);
    ISSUE_STAGE(1);
    ISSUE_STAGE(2);

    for (int s = 0; s < NSTAGE; s++) {
        if (s + 3 < NSTAGE) ISSUE_STAGE(s + 3);
        // require stage s arrived: pending = min(3, NSTAGE-1-s)
        if (s + 4 <= NSTAGE) cpa_wait<3>();
        else if (s + 3 == NSTAGE) cpa_wait<2>();
        else if (s + 2 == NSTAGE) cpa_wait<1>();
        else cpa_wait<0>();
        __syncthreads();

        const uint32_t sb = smb + (s & (NPIPE - 1)) * STG_BYTES;
        const uint32_t arow = (uint32_t)((wm * 64 + (lane & 15)) * LDH_B +
                                         (lane >> 4) * 16);
        const uint32_t brow = (uint32_t)((wn * 32 + ((lane >> 4) & 1) * 8 +
                                          (lane & 7)) * LDH_B +
                                         ((lane >> 3) & 1) * 16);
#pragma unroll
        for (int ks = 0; ks < 2; ks++) {
            uint32_t ah[4][4], al[4][4], bh[4][2], bl[4][2];
#pragma unroll
            for (int mt = 0; mt < 4; mt++) {
                const uint32_t ao = arow + (uint32_t)(mt * 16 * LDH_B + ks * 32);
                ldsm4(ah[mt], sb + OFF_AH + ao);
                ldsm4(al[mt], sb + OFF_AL + ao);
            }
#pragma unroll
            for (int t = 0; t < 2; t++) {
                uint32_t r4[4];
                const uint32_t bo = brow + (uint32_t)(t * 16 * LDH_B + ks * 32);
                ldsm4(r4, sb + OFF_BH + bo);
                bh[2 * t][0] = r4[0]; bh[2 * t][1] = r4[1];
                bh[2 * t + 1][0] = r4[2]; bh[2 * t + 1][1] = r4[3];
                ldsm4(r4, sb + OFF_BL + bo);
                bl[2 * t][0] = r4[0]; bl[2 * t][1] = r4[1];
                bl[2 * t + 1][0] = r4[2]; bl[2 * t + 1][1] = r4[3];
            }
#pragma unroll
            for (int mt = 0; mt < 4; mt++)
#pragma unroll
                for (int nt = 0; nt < 4; nt++) {
                    mma16816(acc[mt][nt], ah[mt], bh[nt][0], bh[nt][1]);
                    mma16816(acc[mt][nt], ah[mt], bl[nt][0], bl[nt][1]);
                    mma16816(acc[mt][nt], al[mt], bh[nt][0], bh[nt][1]);
                }
        }
        __syncthreads();
    }

    // epilogue
    const int rg = lane >> 2, cg = (lane & 3) * 2;
#pragma unroll
    for (int mt = 0; mt < 4; mt++) {
        const int row = bm * 128 + wm * 64 + mt * 16 + rg;
#pragma unroll
        for (int nt = 0; nt < 4; nt++) {
            const int col = bn * 128 + wn * 32 + nt * 8 + cg;
            if (OUTM == 0) {
                *(float2*)(C + (size_t)row * D_DIM + col) =
                    make_float2(acc[mt][nt][0], acc[mt][nt][1]);
                *(float2*)(C + (size_t)(row + 8) * D_DIM + col) =
                    make_float2(acc[mt][nt][2], acc[mt][nt][3]);
            } else {
#pragma unroll
                for (int rh = 0; rh < 2; rh++) {
                    float v0 = acc[mt][nt][2 * rh] * scale;
                    float v1 = acc[mt][nt][2 * rh + 1] * scale;
                    __nv_bfloat16 h0 = __float2bfloat16(v0);
                    __nv_bfloat16 h1 = __float2bfloat16(v1);
                    float l0 = v0 - __bfloat162float(h0);
                    float l1 = v1 - __bfloat162float(h1);
                    const size_t o = (size_t)(row + rh * 8) * D_DIM + col;
                    __nv_bfloat162 hp; hp.x = h0; hp.y = h1;
                    *(uint32_t*)(Ch + o) = *(uint32_t*)&hp;
                    *(uint32_t*)(Cl + o) = packbf(l0, l1);
                }
            }
        }
    }
#undef ISSUE_STAGE
}

// ---------------------------------------------------------------------------
// HMMA flash attention (causal). CTA: 128 q-rows x 1 head. 8 warps x 16 rows.
// Bk=64, K/V double-buffered cp.async with SPLIT K/V commit groups:
// wait K before QK, wait V only before PV (V load hides under QK+softmax).
// bf16x3 for QK and PV. exp2-domain softmax. Writes bf16 hi/lo output.
// ---------------------------------------------------------------------------
#define FQ_BYTES (128 * 144)            // 18432 per Q array
#define FKV_ARR  (64 * 144)             // 9216 per K/V array
#define FKV_STG  (4 * FKV_ARR)          // 36864 per stage
#define FLASH_SMEM (2 * FQ_BYTES + 2 * FKV_STG)   // 110592

__global__ __launch_bounds__(256) void flash_mma(
    const __nv_bfloat16* __restrict__ Qh, const __nv_bfloat16* __restrict__ Ql,
    const __nv_bfloat16* __restrict__ Kh, const __nv_bfloat16* __restrict__ Kl,
    const __nv_bfloat16* __restrict__ Vh, const __nv_bfloat16* __restrict__ Vl,
    __nv_bfloat16* __restrict__ Oh, __nv_bfloat16* __restrict__ Ol)
{
    extern __shared__ char fsm[];
    const uint32_t smb = smem_u32(fsm);
    const int tid = threadIdx.x, lane = tid & 31, wm = tid >> 5;
    const int bq = (int)gridDim.x - 1 - (int)blockIdx.x;   // heavy blocks first
    const int hh = blockIdx.y, bb = blockIdx.z;
    const int q0 = bq * 128;
    const int nt = 2 * bq + 2;
    const size_t rowbase = (size_t)bb * S_LEN;
    const int coff = hh * HD;

    const uint32_t QHs = smb, QLs = smb + FQ_BYTES, KVs = smb + 2 * FQ_BYTES;

    // issue Q tile (joins the first K commit group)
#pragma unroll
    for (int i = 0; i < 4; i++) {
        int id = tid + i * 256;
        int r = id >> 3, c = id & 7;
        size_t g = (rowbase + q0 + r) * D_DIM + coff + c * 8;
        uint32_t d = (uint32_t)(r * 144 + c * 16);
        cpa16(QHs + d, Qh + g);
        cpa16(QLs + d, Ql + g);
    }

#define ISSUE_K(t_, st_)                                                     \
    {                                                                        \
        const uint32_t base_ = KVs + (st_) * FKV_STG;                        \
        const int k0_ = (t_) * 64;                                           \
        _Pragma("unroll")                                                    \
        for (int i = 0; i < 2; i++) {                                        \
            int id = tid + i * 256;                                          \
            int r = id >> 3, c = id & 7;                                     \
            size_t g = (rowbase + k0_ + r) * D_DIM + coff + c * 8;           \
            uint32_t d = (uint32_t)(r * 144 + c * 16);                       \
            cpa16(base_ + d, Kh + g);                                        \
            cpa16(base_ + FKV_ARR + d, Kl + g);                              \
        }                                                                    \
        cpa_commit();                                                        \
    }
#define ISSUE_V(t_, st_)                                                     \
    {                                                                        \
        const uint32_t base_ = KVs + (st_) * FKV_STG;                        \
        const int k0_ = (t_) * 64;                                           \
        _Pragma("unroll")                                                    \
        for (int i = 0; i < 2; i++) {                                        \
            int id = tid + i * 256;                                          \
            int r = id >> 3, c = id & 7;                                     \
            size_t g = (rowbase + k0_ + r) * D_DIM + coff + c * 8;           \
            uint32_t d = (uint32_t)(r * 144 + c * 16);                       \
            cpa16(base_ + 2 * FKV_ARR + d, Vh + g);                          \
            cpa16(base_ + 3 * FKV_ARR + d, Vl + g);                          \
        }                                                                    \
        cpa_commit();                                                        \
    }

    // prologue: groups = {Q+K0}, {V0}, {K1}, {V1}
    ISSUE_K(0, 0);
    ISSUE_V(0, 0);
    ISSUE_K(1, 1);
    ISSUE_V(1, 1);

    // K0 (and Q) ready: pending after group0 = V0,K1,V1 = 3
    cpa_wait<3>();
    __syncthreads();

    // Q fragments -> registers (stay for whole CTA)
    uint32_t qfh[4][4], qfl[4][4];
    {
        const uint32_t qoff = (uint32_t)((wm * 16 + (lane & 15)) * 144 +
                                         ((lane >> 4) & 1) * 16);
#pragma unroll
        for (int k = 0; k < 4; k++) {
            ldsm4(qfh[k], QHs + qoff + k * 32);
            ldsm4(qfl[k], QLs + qoff + k * 32);
        }
    }

    float O[8][4];
#pragma unroll
    for (int j = 0; j < 8; j++)
#pragma unroll
        for (int e = 0; e < 4; e++) O[j][e] = 0.0f;
    float mo[2] = {-1e30f, -1e30f}, ls[2] = {0.0f, 0.0f};

    const int qb = q0 + wm * 16;

    for (int t = 0; t < nt; t++) {
        const uint32_t sb = KVs + (t & 1) * FKV_STG;
        const int k0 = t * 64;

        if (t > 0) {
            // K(t) ready: steady-state pending = V(t),K(t+1),V(t+1)
            if (t < nt - 1) cpa_wait<3>(); else cpa_wait<1>();
            __syncthreads();
        }

        // ---- S = Qs K^T (exp2 domain; scale folded into Q) ----
        float S[8][4];
#pragma unroll
        for (int j = 0; j < 8; j++)
#pragma unroll
            for (int e = 0; e < 4; e++) S[j][e] = 0.0f;

        const uint32_t krow = (uint32_t)(((lane & 7) + ((lane >> 4) & 1) * 8) * 144 +
                                         ((lane >> 3) & 1) * 16);
#pragma unroll
        for (int j2 = 0; j2 < 4; j2++) {
#pragma unroll
            for (int k = 0; k < 4; k++) {
                uint32_t bh[4], bl[4];
                const uint32_t ka = sb + krow + (uint32_t)(j2 * 16 * 144 + k * 32);
                ldsm4(bh, ka);
                ldsm4(bl, ka + FKV_ARR);
                mma16816(S[2 * j2], qfh[k], bh[0], bh[1]);
                mma16816(S[2 * j2], qfh[k], bl[0], bl[1]);
                mma16816(S[2 * j2], qfl[k], bh[0], bh[1]);
                mma16816(S[2 * j2 + 1], qfh[k], bh[2], bh[3]);
                mma16816(S[2 * j2 + 1], qfh[k], bl[2], bl[3]);
                mma16816(S[2 * j2 + 1], qfl[k], bh[2], bh[3]);
            }
        }

        // ---- causal mask ----
        if (k0 + 63 > qb) {
#pragma unroll
            for (int j = 0; j < 8; j++)
#pragma unroll
                for (int e = 0; e < 4; e++) {
                    int kj = k0 + j * 8 + (lane & 3) * 2 + (e & 1);
                    int qi = qb + (lane >> 2) + (e >> 1) * 8;
                    if (kj > qi) S[j][e] = -1e30f;
                }
        }

        // ---- online softmax (exp2 domain), per row-half ----
#pragma unroll
        for (int rh = 0; rh < 2; rh++) {
            float mx = -1e30f;
#pragma unroll
            for (int j = 0; j < 8; j++) {
                mx = fmaxf(mx, S[j][2 * rh]);
                mx = fmaxf(mx, S[j][2 * rh + 1]);
            }
            mx = fmaxf(mx, __shfl_xor_sync(0xffffffffu, mx, 1));
            mx = fmaxf(mx, __shfl_xor_sync(0xffffffffu, mx, 2));
            const float mn = fmaxf(mo[rh], mx);
            const float cc = ex2f(mo[rh] - mn);
            mo[rh] = mn;
            float ps = 0.0f;
#pragma unroll
            for (int j = 0; j < 8; j++) {
                float p0 = ex2f(S[j][2 * rh] - mn);
                float p1 = ex2f(S[j][2 * rh + 1] - mn);
                S[j][2 * rh] = p0;
                S[j][2 * rh + 1] = p1;
                ps += p0 + p1;
            }
            ps += __shfl_xor_sync(0xffffffffu, ps, 1);
            ps += __shfl_xor_sync(0xffffffffu, ps, 2);
            ls[rh] = ls[rh] * cc + ps;
#pragma unroll
            for (int j = 0; j < 8; j++) {
                O[j][2 * rh] *= cc;
                O[j][2 * rh + 1] *= cc;
            }
        }

        // ---- pack P -> A fragments (hi/lo) ----
        uint32_t aph[4][4], apl[4][4];
#pragma unroll
        for (int k = 0; k < 4; k++)
#pragma unroll
            for (int r = 0; r < 4; r++) {
                const int tl = 2 * k + (r >> 1);
                const int pr = (r & 1) * 2;
                float x0 = S[tl][pr], x1 = S[tl][pr + 1];
                __nv_bfloat16 h0 = __float2bfloat16(x0);
                __nv_bfloat16 h1 = __float2bfloat16(x1);
                __nv_bfloat162 hp; hp.x = h0; hp.y = h1;
                aph[k][r] = *(uint32_t*)&hp;
                apl[k][r] = packbf(x0 - __bfloat162float(h0),
                                   x1 - __bfloat162float(h1));
            }

        // V(t) ready: steady-state pending = K(t+1),V(t+1)
        if (t < nt - 1) cpa_wait<2>(); else cpa_wait<0>();
        __syncthreads();

        // ---- O += P V  (V via ldmatrix.trans) ----
        const uint32_t vrow = (uint32_t)(((lane & 7) + ((lane >> 3) & 1) * 8) * 144 +
                                         ((lane >> 4) & 1) * 16);
#pragma unroll
        for (int dj = 0; dj < 4; dj++) {
#pragma unroll
            for (int k = 0; k < 4; k++) {
                uint32_t bh[4], bl[4];
                const uint32_t va = sb + 2 * FKV_ARR + vrow +
                                    (uint32_t)(k * 16 * 144 + dj * 32);
                ldsm4t(bh, va);
                ldsm4t(bl, va + FKV_ARR);
                mma16816(O[2 * dj], aph[k], bh[0], bh[1]);
                mma16816(O[2 * dj], aph[k], bl[0], bl[1]);
                mma16816(O[2 * dj], apl[k], bh[0], bh[1]);
                mma16816(O[2 * dj + 1], aph[k], bh[2], bh[3]);
                mma16816(O[2 * dj + 1], aph[k], bl[2], bl[3]);
                mma16816(O[2 * dj + 1], apl[k], bh[2], bh[3]);
            }
        }

        // buffer (t&1) fully consumed -> prefetch tile t+2 into it
        __syncthreads();
        if (t + 2 < nt) {
            ISSUE_K(t + 2, (t & 1));
            ISSUE_V(t + 2, (t & 1));
        }
    }

    // ---- epilogue: normalize, split, store bf16 hi/lo ----
    const float inv[2] = {1.0f / ls[0], 1.0f / ls[1]};
#pragma unroll
    for (int j = 0; j < 8; j++)
#pragma unroll
        for (int rh = 0; rh < 2; rh++) {
            float o0 = O[j][2 * rh] * inv[rh];
            float o1 = O[j][2 * rh + 1] * inv[rh];
            __nv_bfloat16 h0 = __float2bfloat16(o0);
            __nv_bfloat16 h1 = __float2bfloat16(o1);
            const size_t row = rowbase + q0 + wm * 16 + (lane >> 2) + rh * 8;
            const int col = coff + j * 8 + (lane & 3) * 2;
            __nv_bfloat162 hp; hp.x = h0; hp.y = h1;
            *(uint32_t*)(Oh + row * D_DIM + col) = *(uint32_t*)&hp;
            *(uint32_t*)(Ol + row * D_DIM + col) =
                packbf(o0 - __bfloat162float(h0), o1 - __bfloat162float(h1));
        }
#undef ISSUE_K
#undef ISSUE_V
}

extern "C" void kernel_launch(void* const* d_in, const int* in_sizes, int n_in,
                              void* d_out, int out_size)
{
    (void)in_sizes; (void)n_in; (void)out_size;
    const float* x  = (const float*)d_in[0];
    const float* WQ = (const float*)d_in[1];
    const float* WK = (const float*)d_in[2];
    const float* WV = (const float*)d_in[3];
    const float* WO = (const float*)d_in[4];
    float* out = (float*)d_out;

    __nv_bfloat16 *Xh, *Xl, *Qh, *Ql, *Kh, *Kl, *Vh, *Vl, *AOh, *AOl;
    cudaGetSymbolAddress((void**)&Xh, g_Xh);
    cudaGetSymbolAddress((void**)&Xl, g_Xl);
    cudaGetSymbolAddress((void**)&Qh, g_Qh);
    cudaGetSymbolAddress((void**)&Ql, g_Ql);
    cudaGetSymbolAddress((void**)&Kh, g_Kh);
    cudaGetSymbolAddress((void**)&Kl, g_Kl);
    cudaGetSymbolAddress((void**)&Vh, g_Vh);
    cudaGetSymbolAddress((void**)&Vl, g_Vl);
    cudaGetSymbolAddress((void**)&AOh, g_AOh);
    cudaGetSymbolAddress((void**)&AOl, g_AOl);
    __nv_bfloat16 *WQh, *WQl, *WKh, *WKl, *WVh, *WVl, *WOh, *WOl;
    cudaGetSymbolAddress((void**)&WQh, g_WQh);
    cudaGetSymbolAddress((void**)&WQl, g_WQl);
    cudaGetSymbolAddress((void**)&WKh, g_WKh);
    cudaGetSymbolAddress((void**)&WKl, g_WKl);
    cudaGetSymbolAddress((void**)&WVh, g_WVh);
    cudaGetSymbolAddress((void**)&WVl, g_WVl);
    cudaGetSymbolAddress((void**)&WOh, g_WOh);
    cudaGetSymbolAddress((void**)&WOl, g_WOl);

    // weight transpose+split and activation split
    dim3 tg(D_DIM / 32, D_DIM / 32);
    dim3 tb(32, 8);
    transpose_split<<<tg, tb>>>(WQ, WQh, WQl);
    transpose_split<<<tg, tb>>>(WK, WKh, WKl);
    transpose_split<<<tg, tb>>>(WV, WVh, WVl);
    transpose_split<<<tg, tb>>>(WO, WOh, WOl);
    split_fp32<<<(M_TOT * D_DIM) / (256 * 4), 256>>>(x, Xh, Xl);

    cudaFuncSetAttribute(gemm_mma<0>, cudaFuncAttributeMaxDynamicSharedMemorySize,
                         GEMM_SMEM);
    cudaFuncSetAttribute(gemm_mma<1>, cudaFuncAttributeMaxDynamicSharedMemorySize,
                         GEMM_SMEM);
    dim3 gg(D_DIM / 128, M_TOT / 128);   // (8, 32)
    // projections emit bf16 hi/lo directly; Q carries log2e/8
    gemm_mma<1><<<gg, 256, GEMM_SMEM>>>(Xh, Xl, WQh, WQl, nullptr, Qh, Ql, QSCALE);
    gemm_mma<1><<<gg, 256, GEMM_SMEM>>>(Xh, Xl, WKh, WKl, nullptr, Kh, Kl, 1.0f);
    gemm_mma<1><<<gg, 256, GEMM_SMEM>>>(Xh, Xl, WVh, WVl, nullptr, Vh, Vl, 1.0f);

    cudaFuncSetAttribute(flash_mma, cudaFuncAttributeMaxDynamicSharedMemorySize,
                         FLASH_SMEM);
    flash_mma<<<dim3(S_LEN / 128, H_NUM, B_NUM), 256, FLASH_SMEM>>>(
        Qh, Ql, Kh, Kl, Vh, Vl, AOh, AOl);

    gemm_mma<0><<<gg, 256, GEMM_SMEM>>>(AOh, AOl, WOh, WOl, out, nullptr, nullptr,
                                        1.0f);
}